// round 17
// baseline (speedup 1.0000x reference)
#include <cuda_runtime.h>
#include <cuda_fp16.h>

// Problem constants (from reference)
#define B        4096
#define N_ELEM   2048
#define N_NODES  1024
#define E2       4096
#define G        4                     // batches per group
#define NGROUPS  (B / G)               // 1024 groups
#define NBLK     152                   // 1 CTA/SM, persistent
#define THREADS  1024                  // 1 node per thread

// __device__ scratch (16B-aligned for cp.async.bulk sources).
__device__ __align__(16) uint2 g_csr[E2 + 4];       // {eid, half2(vx,vy)} 8B
__device__ __align__(16) int   g_off[N_NODES + 4];
__device__ __align__(16) int   g_nodeof[N_NODES];   // degree rank -> node id
__device__ int   g_perm[E2];
__device__ float g_part[NBLK];
__device__ int   g_ctr = 0;

// Dynamic smem layout (bytes):
#define OFF_CSR    0                    // uint2[E2+4] = 32800 (reserve 33024)
#define OFF_AXIAL  33024                // float4[2048] = 32768
#define OFF_RES    65792                // float4[2048] = 32768 (ax,ay per node)
#define OFF_BUF0   98560                // 64K: [EA g0..g3 | e g0..g3]
#define OFF_BUF1   164096               // 64K
#define SMEM_BYTES 229632               // + ~160B static < 232448 limit

#define CSR_BYTES   ((E2 + 4) * 8)       // 32800 (multiple of 16)
#define GRP_BYTES   (2 * G * N_ELEM * 4) // 65536

__device__ __forceinline__ unsigned smem_u32(const void* p) {
    return (unsigned)__cvta_generic_to_shared(p);
}
__device__ __forceinline__ void mbar_init(unsigned mbar, unsigned count) {
    asm volatile("mbarrier.init.shared.b64 [%0], %1;" :: "r"(mbar), "r"(count) : "memory");
}
__device__ __forceinline__ void mbar_expect_tx(unsigned mbar, unsigned bytes) {
    asm volatile("mbarrier.arrive.expect_tx.shared.b64 _, [%0], %1;"
                 :: "r"(mbar), "r"(bytes) : "memory");
}
__device__ __forceinline__ void mbar_wait(unsigned mbar, unsigned parity) {
    asm volatile(
        "{\n\t.reg .pred P;\n\t"
        "W%=:\n\t"
        "mbarrier.try_wait.parity.acquire.cta.shared::cta.b64 P, [%0], %1, 0x989680;\n\t"
        "@!P bra W%=;\n\t}"
        :: "r"(mbar), "r"(parity) : "memory");
}
__device__ __forceinline__ void bulk_g2s(unsigned dst_smem, const void* src,
                                         unsigned bytes, unsigned mbar) {
    asm volatile(
        "cp.async.bulk.shared::cta.global.mbarrier::complete_tx::bytes [%0], [%1], %2, [%3];"
        :: "r"(dst_smem), "l"(src), "r"(bytes), "r"(mbar) : "memory");
}

// ---------------------------------------------------------------------------
// Plan: deterministic CSR permutation + offsets + bitonic degree ranking.
// One block, 1024 threads.
// ---------------------------------------------------------------------------
__global__ __launch_bounds__(N_NODES)
void nel_plan_kernel(const int* __restrict__ node_ids) {
    __shared__ int s_beg[N_NODES];
    __shared__ int s_cur[N_NODES];
    __shared__ int s_idx[E2];
    __shared__ int s_key[N_NODES];
    __shared__ int s_wsum[32];
    const int tid  = threadIdx.x;
    const int lane = tid & 31;
    const int wrp  = tid >> 5;

    // 1. histogram
    s_beg[tid] = 0;
    __syncthreads();
    #pragma unroll
    for (int i = tid; i < E2; i += N_NODES)
        atomicAdd(&s_beg[node_ids[i]], 1);
    __syncthreads();

    // 2. exclusive scan via warp shuffles
    const int cnt = s_beg[tid];
    int v = cnt;
    #pragma unroll
    for (int o = 1; o < 32; o <<= 1) {
        int t = __shfl_up_sync(0xffffffffu, v, o);
        if (lane >= o) v += t;
    }
    if (lane == 31) s_wsum[wrp] = v;
    __syncthreads();
    if (wrp == 0) {
        int w = s_wsum[lane];
        #pragma unroll
        for (int o = 1; o < 32; o <<= 1) {
            int t = __shfl_up_sync(0xffffffffu, w, o);
            if (lane >= o) w += t;
        }
        s_wsum[lane] = w - s_wsum[lane];
    }
    __syncthreads();
    const int excl = v - cnt + s_wsum[wrp];
    s_beg[tid] = excl;
    s_cur[tid] = excl;
    // unique key: degree descending, id ascending tiebreak
    s_key[tid] = ((1023 - min(cnt, 1023)) << 10) | tid;
    __syncthreads();

    // 3. scatter edge indices into bins
    #pragma unroll
    for (int i = tid; i < E2; i += N_NODES) {
        int pos = atomicAdd(&s_cur[node_ids[i]], 1);
        s_idx[pos] = i;
    }
    __syncthreads();

    // 4. per-bin insertion sort -> deterministic edge order (bins ~4 entries)
    {
        const int beg = s_beg[tid], end = s_cur[tid];
        for (int a = beg + 1; a < end; a++) {
            int key = s_idx[a];
            int p = a - 1;
            while (p >= beg && s_idx[p] > key) { s_idx[p + 1] = s_idx[p]; p--; }
            s_idx[p + 1] = key;
        }
    }
    __syncthreads();

    // 4b. bitonic sort of 1024 unique keys (fully parallel, deterministic)
    for (int kk = 2; kk <= N_NODES; kk <<= 1) {
        for (int j = kk >> 1; j > 0; j >>= 1) {
            int ixj = tid ^ j;
            if (ixj > tid) {
                int a = s_key[tid], b2 = s_key[ixj];
                bool up = ((tid & kk) == 0);
                if ((a > b2) == up) { s_key[tid] = b2; s_key[ixj] = a; }
            }
            __syncthreads();
        }
    }

    // 5. write outputs
    g_off[tid]    = s_beg[tid];
    g_nodeof[tid] = s_key[tid] & 1023;
    if (tid == 0) {
        g_off[N_NODES] = E2; g_off[N_NODES + 1] = E2;
        g_off[N_NODES + 2] = E2; g_off[N_NODES + 3] = E2;
    }
    #pragma unroll
    for (int i = tid; i < E2; i += N_NODES)
        g_perm[i] = s_idx[i];
}

// ---------------------------------------------------------------------------
// Materialize: write fused 8B CSR records {eid, half2(vx,vy)} in parallel.
// ---------------------------------------------------------------------------
__global__ __launch_bounds__(256)
void nel_mat_kernel(const int* __restrict__ elem_ids,
                    const float* __restrict__ vecs) {
    int i = blockIdx.x * 256 + threadIdx.x;
    if (i < E2) {
        int idx = g_perm[i];
        __half2 h = __floats2half2_rn(vecs[2 * idx], vecs[2 * idx + 1]);
        uint2 rec;
        rec.x = (unsigned)elem_ids[idx];
        rec.y = *reinterpret_cast<unsigned*>(&h);
        g_csr[i] = rec;
    } else if (i < E2 + 4) {
        uint2 rec; rec.x = 0; rec.y = 0;   // dummy: eid 0, weights 0
        g_csr[i] = rec;
    }
}

// ---------------------------------------------------------------------------
// Main: 152 persistent blocks (1/SM), 1024 threads, G=4 batches per group.
// Degree-sorted gather (slots ~= mean degree) -> s_res; separate coalesced
// loss phase (node order). TMA double-buffer EA/e; 8B CSR records.
// ---------------------------------------------------------------------------
__global__ __launch_bounds__(THREADS, 1)
void nel_main_kernel(const float* __restrict__ EA,
                     const float* __restrict__ e,
                     const float* __restrict__ q,
                     const float* __restrict__ r,
                     float* __restrict__ out) {
    extern __shared__ unsigned char dyn[];
    uint2*  s_csr   = (uint2*) (dyn + OFF_CSR);
    float4* s_axial = (float4*)(dyn + OFF_AXIAL);
    float4* s_res   = (float4*)(dyn + OFF_RES);    // [2*node+0]=ax, [2*node+1]=ay
    float*  s_buf0  = (float*) (dyn + OFF_BUF0);
    float*  s_buf1  = (float*) (dyn + OFF_BUF1);
    __shared__ __align__(8) unsigned long long s_mbar[2];
    __shared__ float s_warp[THREADS / 32];
    __shared__ int   s_islast;

    const int tid = threadIdx.x;
    const int g0  = blockIdx.x;
    const int cnt = (NGROUPS - g0 + NBLK - 1) / NBLK;
    const unsigned mb0 = smem_u32(&s_mbar[0]);
    const unsigned mb1 = smem_u32(&s_mbar[1]);

    if (tid == 0) { mbar_init(mb0, 1); mbar_init(mb1, 1); }
    __syncthreads();

    // gather assignment: degree-ranked node; loss assignment: node tid.
    const int n   = __ldg(&g_nodeof[tid]);
    const int beg = __ldg(&g_off[n]);
    const int len = __ldg(&g_off[n + 1]) - beg;
    int m = len;                         // warp-uniform bound (~mean degree)
    #pragma unroll
    for (int o = 16; o > 0; o >>= 1)
        m = max(m, __shfl_xor_sync(0xffffffffu, m, o));

    // --- prologue: CSR + group 0 on mb0, group 1 on mb1 ---
    if (tid == 0) {
        {
            int grp = g0;
            mbar_expect_tx(mb0, CSR_BYTES + GRP_BYTES);
            bulk_g2s(smem_u32(s_csr), g_csr, CSR_BYTES, mb0);
            bulk_g2s(smem_u32(s_buf0),
                     EA + (size_t)grp * G * N_ELEM, G * N_ELEM * 4, mb0);
            bulk_g2s(smem_u32(s_buf0 + G * N_ELEM),
                     e  + (size_t)grp * G * N_ELEM, G * N_ELEM * 4, mb0);
        }
        if (cnt > 1) {
            int grp = g0 + NBLK;
            mbar_expect_tx(mb1, GRP_BYTES);
            bulk_g2s(smem_u32(s_buf1),
                     EA + (size_t)grp * G * N_ELEM, G * N_ELEM * 4, mb1);
            bulk_g2s(smem_u32(s_buf1 + G * N_ELEM),
                     e  + (size_t)grp * G * N_ELEM, G * N_ELEM * 4, mb1);
        }
    }

    float acc = 0.f;
    unsigned ph0 = 0, ph1 = 0;

    for (int k = 0; k < cnt; k++) {
        const int grp  = g0 + k * NBLK;
        const int bsel = k & 1;
        float* buf = bsel ? s_buf1 : s_buf0;
        const unsigned mb = bsel ? mb1 : mb0;

        // --- early-issue COALESCED q/r for loss node tid; fold t=q+r ---
        const float2* q2 = (const float2*)(q + (size_t)grp * G * N_NODES * 2);
        const float2* r2 = (const float2*)(r + (size_t)grp * G * N_NODES * 2);
        float2 t[G];
        #pragma unroll
        for (int g = 0; g < G; g++) {
            float2 qq = __ldg(&q2[g * N_NODES + tid]);
            float2 rr = __ldg(&r2[g * N_NODES + tid]);
            t[g] = make_float2(qq.x + rr.x, qq.y + rr.y);
        }

        if (bsel) { mbar_wait(mb, ph1); ph1 ^= 1; }
        else      { mbar_wait(mb, ph0); ph0 ^= 1; }

        // --- build axial4[i] = {EA_g*e_g} for g=0..3 (2 iters/thread) ---
        #pragma unroll
        for (int i = tid; i < N_ELEM; i += THREADS) {
            float4 a;
            a.x = buf[0 * N_ELEM + i] * buf[(G + 0) * N_ELEM + i];
            a.y = buf[1 * N_ELEM + i] * buf[(G + 1) * N_ELEM + i];
            a.z = buf[2 * N_ELEM + i] * buf[(G + 2) * N_ELEM + i];
            a.w = buf[3 * N_ELEM + i] * buf[(G + 3) * N_ELEM + i];
            s_axial[i] = a;
        }
        __syncthreads();   // axial ready; buf free for refill

        // --- refill this buffer with group k+2 (overlaps gather) ---
        if (tid == 0 && k + 2 < cnt) {
            int ng = g0 + (k + 2) * NBLK;
            mbar_expect_tx(mb, GRP_BYTES);
            bulk_g2s(smem_u32(buf),
                     EA + (size_t)ng * G * N_ELEM, G * N_ELEM * 4, mb);
            bulk_g2s(smem_u32(buf + G * N_ELEM),
                     e  + (size_t)ng * G * N_ELEM, G * N_ELEM * 4, mb);
        }

        // --- gather (degree-ranked node): uniform bound, unroll-4 ---
        float4 ax = make_float4(0.f, 0.f, 0.f, 0.f);
        float4 ay = make_float4(0.f, 0.f, 0.f, 0.f);
        for (int c = 0; c < m; c += 4) {
            #pragma unroll
            for (int u = 0; u < 4; u++) {
                int off = c + u;
                int idx = (off < len) ? (beg + off) : E2;     // dummy if past end
                uint2 rec = s_csr[idx];                        // LDS.64
                __half2 h = *reinterpret_cast<__half2*>(&rec.y);
                float2 vv = __half22float2(h);
                float4 a  = s_axial[rec.x];                    // LDS.128
                ax.x += a.x * vv.x;  ax.y += a.y * vv.x;
                ax.z += a.z * vv.x;  ax.w += a.w * vv.x;
                ay.x += a.x * vv.y;  ay.y += a.y * vv.y;
                ay.z += a.z * vv.y;  ay.w += a.w * vv.y;
            }
        }
        s_res[2 * n + 0] = ax;
        s_res[2 * n + 1] = ay;
        __syncthreads();   // res complete

        // --- loss (node tid, fully coalesced) ---
        float4 rx = s_res[2 * tid + 0];
        float4 ry = s_res[2 * tid + 1];
        const float* rxp = (const float*)&rx;
        const float* ryp = (const float*)&ry;
        #pragma unroll
        for (int g = 0; g < G; g++) {
            float dx = rxp[g] - t[g].x;
            float dy = ryp[g] - t[g].y;
            acc += dx * dx + dy * dy;
        }
        __syncthreads();   // axial/res consumed before next group overwrites
    }

    // --- block reduce ---
    #pragma unroll
    for (int o = 16; o > 0; o >>= 1)
        acc += __shfl_down_sync(0xffffffffu, acc, o);
    if ((tid & 31) == 0) s_warp[tid >> 5] = acc;
    __syncthreads();
    if (tid == 0) {
        float total = 0.f;
        #pragma unroll
        for (int w = 0; w < THREADS / 32; w++) total += s_warp[w];
        g_part[blockIdx.x] = total;
    }

    // --- last-block finalize (fixed-order double sum -> deterministic) ---
    __threadfence();
    if (tid == 0) {
        int old = atomicAdd(&g_ctr, 1);
        s_islast = (old == (int)gridDim.x - 1) ? 1 : 0;
    }
    __syncthreads();
    if (s_islast) {
        __threadfence();
        double* s_d = (double*)(dyn + OFF_RES);   // overlay consumed res region
        double d = 0.0;
        #pragma unroll
        for (int i = tid; i < NBLK; i += THREADS) d += (double)g_part[i];
        s_d[tid] = d;
        __syncthreads();
        #pragma unroll
        for (int s = THREADS / 2; s > 0; s >>= 1) {
            if (tid < s) s_d[tid] += s_d[tid + s];
            __syncthreads();
        }
        if (tid == 0) {
            out[0] = (float)(s_d[0] / ((double)B * (double)N_NODES * 2.0));
            g_ctr = 0;   // reset for next graph replay
        }
    }
}

extern "C" void kernel_launch(void* const* d_in, const int* in_sizes, int n_in,
                              void* d_out, int out_size) {
    const float* EA       = (const float*)d_in[0];
    const float* e        = (const float*)d_in[1];
    const float* q        = (const float*)d_in[2];
    const float* r        = (const float*)d_in[3];
    const float* vecs     = (const float*)d_in[4];
    const int*   node_ids = (const int*)d_in[5];
    const int*   elem_ids = (const int*)d_in[6];
    float* out = (float*)d_out;

    static int configured = 0;
    if (!configured) {
        cudaFuncSetAttribute(nel_main_kernel,
                             cudaFuncAttributeMaxDynamicSharedMemorySize,
                             SMEM_BYTES);
        configured = 1;
    }

    nel_plan_kernel<<<1, N_NODES>>>(node_ids);
    nel_mat_kernel<<<(E2 + 4 + 255) / 256, 256>>>(elem_ids, vecs);
    nel_main_kernel<<<NBLK, THREADS, SMEM_BYTES>>>(EA, e, q, r, out);
}